// round 8
// baseline (speedup 1.0000x reference)
#include <cuda_runtime.h>
#include <cuda_fp16.h>
#include <cstdint>

constexpr int Bn = 8, Cn = 128, Tn = 32768, Ln = 256;
constexpr float SLOPE = 0.2f;
constexpr int NT = 1024;

// ---- device scratch ----
__device__ __half gA  [(size_t)Bn * Ln * 3 * Cn * Cn];  // lvc weight [b][l][k][co][ci] fp16
__device__ __half g_h [(size_t)Bn * Cn * Tn];           // LVC output fp16
__device__ __half gA2 [3 * Cn * Cn];                    // dconv weight [k][co][ci] fp16

// ---- helpers ----
static __device__ __forceinline__ uint32_t smem_u32(const void* p) {
    uint32_t a;
    asm("{ .reg .u64 t; cvta.to.shared.u64 t, %1; cvt.u32.u64 %0, t; }" : "=r"(a) : "l"(p));
    return a;
}
static __device__ __forceinline__ void ldm_x4(uint32_t &r0, uint32_t &r1,
                                              uint32_t &r2, uint32_t &r3, uint32_t addr) {
    asm volatile("ldmatrix.sync.aligned.m8n8.x4.shared.b16 {%0,%1,%2,%3}, [%4];"
                 : "=r"(r0), "=r"(r1), "=r"(r2), "=r"(r3) : "r"(addr));
}
static __device__ __forceinline__ void mma16816(float* c, const uint32_t* a, const uint32_t* b) {
    asm volatile("mma.sync.aligned.m16n8k16.row.col.f32.f16.f16.f32 "
                 "{%0,%1,%2,%3}, {%4,%5,%6,%7}, {%8,%9}, {%0,%1,%2,%3};"
                 : "+f"(c[0]), "+f"(c[1]), "+f"(c[2]), "+f"(c[3])
                 : "r"(a[0]), "r"(a[1]), "r"(a[2]), "r"(a[3]), "r"(b[0]), "r"(b[1]));
}
static __device__ __forceinline__ void cpasync16(uint32_t s, const void* g) {
    asm volatile("cp.async.cg.shared.global [%0], [%1], 16;" :: "r"(s), "l"(g));
}
static __device__ __forceinline__ void cp_commit() {
    asm volatile("cp.async.commit_group;" ::: "memory");
}
static __device__ __forceinline__ void cp_wait0() {
    asm volatile("cp.async.wait_group 0;" ::: "memory");
}

constexpr uint32_t ATILE = 34816u;          // 128 rows x 272B
constexpr uint32_t LVC_AOFF = 258u * 272u;  // 70176
constexpr uint32_t SMEM_LVC = LVC_AOFF + 3u * ATILE;   // 174624
constexpr uint32_t DCV_AOFF = 262u * 272u;  // 71264
constexpr uint32_t SMEM_DCV = DCV_AOFF + 3u * ATILE;   // 175712

// stage 3 A tiles (48KB x2 halves... 96KB) into smem rows of 272B via cp.async
static __device__ __forceinline__ void stage_A(uint32_t smb, uint32_t aoff,
                                               const __half* Aw, int tid) {
    const uint4* sA = (const uint4*)Aw;
    #pragma unroll
    for (int j = 0; j < 6; ++j) {
        int i = tid + j * NT;                 // [0, 6144)
        int k = i >> 11, r = i & 2047;
        int co = r >> 4, c8 = (r & 15) << 3;
        cpasync16(smb + aoff + (uint32_t)k * ATILE + (uint32_t)co * 272u + (uint32_t)c8 * 2u,
                  sA + i);
    }
    cp_commit();
}

// ---- prep: weight-norm conv weight -> fp16 [k][co][ci] ----
__global__ void wn_prep_kernel(const float* __restrict__ conv_v,
                               const float* __restrict__ conv_g) {
    __shared__ float sc[Cn];
    int co = threadIdx.x;
    float s = 0.f;
    for (int i = 0; i < Cn * 3; ++i) {
        float t = conv_v[co * (Cn * 3) + i];
        s += t * t;
    }
    sc[co] = conv_g[co] / sqrtf(s);
    __syncthreads();
    for (int i = threadIdx.x; i < 3 * Cn * Cn; i += Cn) {
        int k = i >> 14, rest = i & 16383, c2 = rest >> 7, ci = rest & 127;
        gA2[i] = __float2half_rn(conv_v[(c2 * Cn + ci) * 3 + k] * sc[c2]);
    }
}

// ---- transpose W[b][ci][co][k][l] -> gA[b][l][k][co][ci] fp16 ----
__global__ __launch_bounds__(512)
void transpose_w_kernel(const float* __restrict__ W) {
    __shared__ float tile[64][33];
    int z = blockIdx.z;
    int k = z % 3, co = (z / 3) & 127, b = z / (3 * Cn);
    int l0 = blockIdx.x * 32, ci0 = blockIdx.y * 64;
    const int tid = threadIdx.x;
    #pragma unroll
    for (int j = 0; j < 4; ++j) {
        int i = tid + j * 512;
        int cir = i >> 5, lc = i & 31;
        tile[cir][lc] =
            W[((((size_t)b * Cn + ci0 + cir) * Cn + co) * 3 + k) * Ln + l0 + lc];
    }
    __syncthreads();
    #pragma unroll
    for (int j = 0; j < 4; ++j) {
        int i = tid + j * 512;
        int lr = i >> 6, cic = i & 63;
        size_t o = ((((size_t)b * Ln + l0 + lr) * 3 + k) * Cn + co) * Cn + ci0 + cic;
        gA[o] = __float2half_rn(tile[cic][lr]);
    }
}

// ---- LVC: 256-wide CTA, two 128-wide phases (per-l weights), warp tile 32x16 ----
__global__ __launch_bounds__(NT)
void lvc_kernel(const float* __restrict__ x, const __half* __restrict__ Aw,
                const float* __restrict__ bias, __half* __restrict__ dst) {
    extern __shared__ char sm[];
    const uint32_t smb = smem_u32(sm);
    const int tid = threadIdx.x;
    const int b = blockIdx.x >> 7, tt = blockIdx.x & 127;
    const int t0 = tt * 256;

    // prefetch A(l = 2*tt) while staging the window
    stage_A(smb, LVC_AOFF, Aw + (size_t)(b * Ln + tt * 2) * 49152, tid);

    // window transposed fp16: xT[c][ci], c in [0,258), t = t0-1+c, row stride 272B
    for (int i = tid; i < 64 * 258; i += NT) {
        int cp = i / 258, c = i - cp * 258;
        int t = t0 - 1 + c;
        int ci = cp * 2;
        float v0 = 0.f, v1 = 0.f;
        if (t >= 0 && t < Tn) {
            v0 = x[(size_t)(b * Cn + ci) * Tn + t];
            v1 = x[(size_t)(b * Cn + ci + 1) * Tn + t];
        }
        *(__half2*)(sm + (uint32_t)c * 272u + (uint32_t)ci * 2u) = __floats2half2_rn(v0, v1);
    }
    cp_wait0();
    __syncthreads();

    const int warp = tid >> 5, lane = tid & 31;
    const int co0 = (warp >> 3) * 32, s0 = (warp & 7) * 16;
    const uint32_t lrow = lane & 15, lcol = (uint32_t)(lane >> 4) << 4;
    const int g = lane >> 2, q = lane & 3;

    uint32_t aoffs[2];
    #pragma unroll
    for (int mi = 0; mi < 2; ++mi)
        aoffs[mi] = smb + LVC_AOFF + (uint32_t)(co0 + mi * 16 + (int)lrow) * 272u + lcol;

    #pragma unroll
    for (int p = 0; p < 2; ++p) {
        const uint32_t boff = smb + (uint32_t)(p * 128 + s0 + (int)lrow) * 272u + lcol;
        float acc[2][2][4];
        #pragma unroll
        for (int mi = 0; mi < 2; ++mi)
            #pragma unroll
            for (int ni = 0; ni < 2; ++ni)
                #pragma unroll
                for (int qq = 0; qq < 4; ++qq) acc[mi][ni][qq] = 0.f;

        #pragma unroll
        for (int k = 0; k < 3; ++k) {
            const uint32_t ak = (uint32_t)k * ATILE;
            const uint32_t bk = (uint32_t)k * 272u;
            #pragma unroll
            for (int ch = 0; ch < 8; ++ch) {
                const uint32_t cb = (uint32_t)ch * 32u;
                uint32_t af[2][4];
                #pragma unroll
                for (int mi = 0; mi < 2; ++mi)
                    ldm_x4(af[mi][0], af[mi][1], af[mi][2], af[mi][3], aoffs[mi] + ak + cb);
                uint32_t r0, r1, r2, r3;
                ldm_x4(r0, r1, r2, r3, boff + bk + cb);
                uint32_t bf[2][2] = {{r0, r2}, {r1, r3}};
                #pragma unroll
                for (int mi = 0; mi < 2; ++mi)
                    #pragma unroll
                    for (int ni = 0; ni < 2; ++ni)
                        mma16816(acc[mi][ni], af[mi], bf[ni]);
            }
        }

        // restage A(l+1) NOW; overlap its flight with the epilogue below
        if (p == 0) {
            __syncthreads();   // all warps done reading A for phase 0
            stage_A(smb, LVC_AOFF, Aw + (size_t)(b * Ln + tt * 2 + 1) * 49152, tid);
        }

        // epilogue: bias + leaky -> fp16 g_h
        const int l = tt * 2 + p;
        #pragma unroll
        for (int mi = 0; mi < 2; ++mi)
            #pragma unroll
            for (int h = 0; h < 2; ++h) {
                int co = co0 + mi * 16 + g + h * 8;
                float bv = bias[(size_t)(b * Cn + co) * Ln + l];
                #pragma unroll
                for (int ni = 0; ni < 2; ++ni) {
                    int s = s0 + ni * 8 + q * 2;
                    float v0 = acc[mi][ni][2 * h]     + bv;
                    float v1 = acc[mi][ni][2 * h + 1] + bv;
                    v0 = fmaxf(v0, SLOPE * v0);
                    v1 = fmaxf(v1, SLOPE * v1);
                    size_t off = (size_t)(b * Cn + co) * Tn + t0 + p * 128 + s;
                    *(__half2*)(dst + off) = __floats2half2_rn(v0, v1);
                }
            }

        if (p == 0) {
            cp_wait0();
            __syncthreads();
        }
    }
}

// ---- dconv: 256-wide CTA, one-shot, warp tile 32x32 ----
__global__ __launch_bounds__(NT)
void dconv_kernel(const __half* __restrict__ src, const __half* __restrict__ Aw,
                  const float* __restrict__ conv_b, float* __restrict__ out) {
    extern __shared__ char sm[];
    const uint32_t smb = smem_u32(sm);
    const int tid = threadIdx.x;
    const int b = blockIdx.x >> 7, tt = blockIdx.x & 127;
    const int t0 = tt * 256;

    stage_A(smb, DCV_AOFF, Aw, tid);

    // window transposed: xT[c][ci], c in [0,262), t = t0-3+c
    for (int i = tid; i < 64 * 262; i += NT) {
        int cp = i / 262, c = i - cp * 262;
        int t = t0 - 3 + c;
        int ci = cp * 2;
        __half v0 = __ushort_as_half(0), v1 = __ushort_as_half(0);
        if (t >= 0 && t < Tn) {
            v0 = src[(size_t)(b * Cn + ci) * Tn + t];
            v1 = src[(size_t)(b * Cn + ci + 1) * Tn + t];
        }
        __half2 hv; hv.x = v0; hv.y = v1;
        *(__half2*)(sm + (uint32_t)c * 272u + (uint32_t)ci * 2u) = hv;
    }
    cp_wait0();
    __syncthreads();

    const int warp = tid >> 5, lane = tid & 31;
    const int co0 = (warp >> 3) * 32, s0 = (warp & 7) * 32;
    const uint32_t lrow = lane & 15, lcol = (uint32_t)(lane >> 4) << 4;
    const int g = lane >> 2, q = lane & 3;

    uint32_t aoffs[2], boffs[2];
    #pragma unroll
    for (int mi = 0; mi < 2; ++mi)
        aoffs[mi] = smb + DCV_AOFF + (uint32_t)(co0 + mi * 16 + (int)lrow) * 272u + lcol;
    #pragma unroll
    for (int p = 0; p < 2; ++p)
        boffs[p] = smb + (uint32_t)(s0 + p * 16 + (int)lrow) * 272u + lcol;

    float acc[2][4][4];
    #pragma unroll
    for (int mi = 0; mi < 2; ++mi)
        #pragma unroll
        for (int ni = 0; ni < 4; ++ni)
            #pragma unroll
            for (int qq = 0; qq < 4; ++qq) acc[mi][ni][qq] = 0.f;

    #pragma unroll
    for (int k = 0; k < 3; ++k) {
        const uint32_t ak = (uint32_t)k * ATILE;
        const uint32_t bk = (uint32_t)(3 * k) * 272u;
        #pragma unroll
        for (int ch = 0; ch < 8; ++ch) {
            const uint32_t cb = (uint32_t)ch * 32u;
            uint32_t af[2][4];
            #pragma unroll
            for (int mi = 0; mi < 2; ++mi)
                ldm_x4(af[mi][0], af[mi][1], af[mi][2], af[mi][3], aoffs[mi] + ak + cb);
            #pragma unroll
            for (int p = 0; p < 2; ++p) {
                uint32_t r0, r1, r2, r3;
                ldm_x4(r0, r1, r2, r3, boffs[p] + bk + cb);
                uint32_t bf[2][2] = {{r0, r2}, {r1, r3}};
                #pragma unroll
                for (int mi = 0; mi < 2; ++mi)
                    #pragma unroll
                    for (int nj = 0; nj < 2; ++nj)
                        mma16816(acc[mi][2 * p + nj], af[mi], bf[nj]);
            }
        }
    }

    // epilogue: bias + leaky -> fp32 out
    #pragma unroll
    for (int mi = 0; mi < 2; ++mi)
        #pragma unroll
        for (int h = 0; h < 2; ++h) {
            int co = co0 + mi * 16 + g + h * 8;
            float bv = conv_b[co];
            #pragma unroll
            for (int ni = 0; ni < 4; ++ni) {
                int s = s0 + ni * 8 + q * 2;
                float v0 = acc[mi][ni][2 * h]     + bv;
                float v1 = acc[mi][ni][2 * h + 1] + bv;
                v0 = fmaxf(v0, SLOPE * v0);
                v1 = fmaxf(v1, SLOPE * v1);
                *(float2*)(out + (size_t)(b * Cn + co) * Tn + t0 + s) = make_float2(v0, v1);
            }
        }
}

// ---- launch ----
extern "C" void kernel_launch(void* const* d_in, const int* in_sizes, int n_in,
                              void* d_out, int out_size) {
    const float* x      = (const float*)d_in[0];
    const float* weight = (const float*)d_in[1];
    const float* bias   = (const float*)d_in[2];
    const float* conv_v = (const float*)d_in[3];
    const float* conv_g = (const float*)d_in[4];
    const float* conv_b = (const float*)d_in[5];

    __half *gh_ptr, *pA, *pA2;
    cudaGetSymbolAddress((void**)&gh_ptr, g_h);
    cudaGetSymbolAddress((void**)&pA, gA);
    cudaGetSymbolAddress((void**)&pA2, gA2);

    cudaFuncSetAttribute((const void*)lvc_kernel,
                         cudaFuncAttributeMaxDynamicSharedMemorySize, SMEM_LVC);
    cudaFuncSetAttribute((const void*)dconv_kernel,
                         cudaFuncAttributeMaxDynamicSharedMemorySize, SMEM_DCV);

    wn_prep_kernel<<<1, Cn>>>(conv_v, conv_g);
    transpose_w_kernel<<<dim3(Ln / 32, Cn / 64, Bn * Cn * 3), dim3(512)>>>(weight);
    lvc_kernel<<<Bn * 128, NT, SMEM_LVC>>>(x, pA, bias, gh_ptr);
    dconv_kernel<<<Bn * 128, NT, SMEM_DCV>>>(gh_ptr, pA2, conv_b, (float*)d_out);
}

// round 9
// speedup vs baseline: 1.4262x; 1.4262x over previous
#include <cuda_runtime.h>
#include <cuda_fp16.h>
#include <cstdint>

constexpr int Bn = 8, Cn = 128, Tn = 32768, Ln = 256;
constexpr float SLOPE = 0.2f;
constexpr int NT = 1024;

// ---- device scratch ----
__device__ __half gA  [(size_t)Bn * Ln * 3 * Cn * Cn];  // lvc weight [b][l][k][co][ci] fp16
__device__ __half g_h [(size_t)Bn * Cn * Tn];           // LVC output fp16
__device__ __half gA2 [3 * Cn * Cn];                    // dconv weight [k][co][ci] fp16

// ---- helpers ----
static __device__ __forceinline__ uint32_t smem_u32(const void* p) {
    uint32_t a;
    asm("{ .reg .u64 t; cvta.to.shared.u64 t, %1; cvt.u32.u64 %0, t; }" : "=r"(a) : "l"(p));
    return a;
}
static __device__ __forceinline__ void ldm_x4(uint32_t &r0, uint32_t &r1,
                                              uint32_t &r2, uint32_t &r3, uint32_t addr) {
    asm volatile("ldmatrix.sync.aligned.m8n8.x4.shared.b16 {%0,%1,%2,%3}, [%4];"
                 : "=r"(r0), "=r"(r1), "=r"(r2), "=r"(r3) : "r"(addr));
}
static __device__ __forceinline__ void mma16816(float* c, const uint32_t* a, const uint32_t* b) {
    asm volatile("mma.sync.aligned.m16n8k16.row.col.f32.f16.f16.f32 "
                 "{%0,%1,%2,%3}, {%4,%5,%6,%7}, {%8,%9}, {%0,%1,%2,%3};"
                 : "+f"(c[0]), "+f"(c[1]), "+f"(c[2]), "+f"(c[3])
                 : "r"(a[0]), "r"(a[1]), "r"(a[2]), "r"(a[3]), "r"(b[0]), "r"(b[1]));
}
static __device__ __forceinline__ void cpasync16(uint32_t s, const void* g) {
    asm volatile("cp.async.cg.shared.global [%0], [%1], 16;" :: "r"(s), "l"(g));
}
static __device__ __forceinline__ void cp_commit() {
    asm volatile("cp.async.commit_group;" ::: "memory");
}
static __device__ __forceinline__ void cp_wait0() {
    asm volatile("cp.async.wait_group 0;" ::: "memory");
}

constexpr uint32_t ATILE = 34816u;          // 128 rows x 272B

// ---- lvc smem (R7 layout): fp32 window [0,69120); A at ABASE; xT at XH ----
constexpr uint32_t ABASE = 69632u;
constexpr uint32_t XH    = ABASE + 3u * ATILE;     // 174080
constexpr uint32_t SMEM_LVC = XH + 36448u;         // 210528
constexpr int WSTR = 135;

// ---- dconv smem: xT [0, 71264) (262 rows x 272B); scratch fp32 & A both at 71264 ----
constexpr uint32_t DSOFF = 71264u;
constexpr uint32_t SMEM_DCV = DSOFF + 3u * ATILE;  // 175712
constexpr int WSTR2 = 131;

// ---- prep: weight-norm conv weight -> fp16 [k][co][ci] ----
__global__ void wn_prep_kernel(const float* __restrict__ conv_v,
                               const float* __restrict__ conv_g) {
    __shared__ float sc[Cn];
    int co = threadIdx.x;
    float s = 0.f;
    for (int i = 0; i < Cn * 3; ++i) {
        float t = conv_v[co * (Cn * 3) + i];
        s += t * t;
    }
    sc[co] = conv_g[co] / sqrtf(s);
    __syncthreads();
    for (int i = threadIdx.x; i < 3 * Cn * Cn; i += Cn) {
        int k = i >> 14, rest = i & 16383, c2 = rest >> 7, ci = rest & 127;
        gA2[i] = __float2half_rn(conv_v[(c2 * Cn + ci) * 3 + k] * sc[c2]);
    }
}

// ---- transpose W[b][ci][co][k][l] -> gA[b][l][k][co][ci] fp16 ----
__global__ __launch_bounds__(512)
void transpose_w_kernel(const float* __restrict__ W) {
    __shared__ float tile[64][33];
    int z = blockIdx.z;
    int k = z % 3, co = (z / 3) & 127, b = z / (3 * Cn);
    int l0 = blockIdx.x * 32, ci0 = blockIdx.y * 64;
    const int tid = threadIdx.x;
    #pragma unroll
    for (int j = 0; j < 4; ++j) {
        int i = tid + j * 512;
        int cir = i >> 5, lc = i & 31;
        tile[cir][lc] =
            W[((((size_t)b * Cn + ci0 + cir) * Cn + co) * 3 + k) * Ln + l0 + lc];
    }
    __syncthreads();
    #pragma unroll
    for (int j = 0; j < 4; ++j) {
        int i = tid + j * 512;
        int lr = i >> 6, cic = i & 63;
        size_t o = ((((size_t)b * Ln + l0 + lr) * 3 + k) * Cn + co) * Cn + ci0 + cic;
        gA[o] = __float2half_rn(tile[cic][lr]);
    }
}

// ---- LVC kernel: exactly R7 structure (128-wide CTA, single-pass fp16 HMMA) ----
__global__ __launch_bounds__(NT, 1)
void lvc_kernel(const float* __restrict__ x, const __half* __restrict__ Aw,
                const float* __restrict__ bias, __half* __restrict__ dst) {
    extern __shared__ char sm[];
    const uint32_t smb = smem_u32(sm);
    const int tid = threadIdx.x;
    const int b = blockIdx.x >> 8, tile = blockIdx.x & 255;

    // 1) stage fp32 window coalesced  (130 cols, t = tile*128 - 1 + c)
    {
        float* ws = (float*)sm;
        const int tb = tile * 128 - 1;
        for (int i = tid; i < Cn * 130; i += NT) {
            int ci = i / 130, c = i - ci * 130;
            int t = tb + c;
            ws[ci * WSTR + c] = (t >= 0 && t < Tn)
                ? x[(size_t)(b * Cn + ci) * Tn + t] : 0.f;
        }
    }

    // 2) cp.async all three A tiles
    {
        const uint4* sA = (const uint4*)(Aw + (size_t)(b * Ln + tile) * 49152);
        #pragma unroll
        for (int j = 0; j < 6; ++j) {
            int i = tid + j * NT;
            int k = i >> 11, r = i & 2047;
            int co = r >> 4, c8 = (r & 15) << 3;
            cpasync16(smb + ABASE + (uint32_t)k * ATILE
                      + (uint32_t)co * 272u + (uint32_t)c8 * 2u, sA + i);
        }
        cp_commit();
    }
    __syncthreads();

    // 3) transpose window -> xT fp16 [c][ci]
    {
        const float* ws = (const float*)sm;
        __half* xh = (__half*)(sm + XH);
        for (int i = tid; i < Cn * 130; i += NT) {
            int c = i >> 7, ci = i & 127;
            xh[c * 136 + ci] = __float2half_rn(ws[ci * WSTR + c]);
        }
    }
    cp_wait0();
    __syncthreads();

    const int warp = tid >> 5, lane = tid & 31;
    const int co0 = (warp >> 3) * 32, s0 = (warp & 7) * 16;
    const uint32_t lrow = lane & 15, lcol = (uint32_t)(lane >> 4) << 4;

    float acc[2][2][4];
    #pragma unroll
    for (int mi = 0; mi < 2; ++mi)
        #pragma unroll
        for (int ni = 0; ni < 2; ++ni)
            #pragma unroll
            for (int q = 0; q < 4; ++q) acc[mi][ni][q] = 0.f;

    uint32_t aoffs[2];
    #pragma unroll
    for (int mi = 0; mi < 2; ++mi)
        aoffs[mi] = smb + ABASE + (uint32_t)(co0 + mi * 16 + (int)lrow) * 272u + lcol;
    const uint32_t boff = smb + XH + (uint32_t)(s0 + (int)lrow) * 272u + lcol;

    #pragma unroll
    for (int k = 0; k < 3; ++k) {
        const uint32_t ak = (uint32_t)k * ATILE;
        const uint32_t bk = (uint32_t)k * 272u;
        #pragma unroll
        for (int ch = 0; ch < 8; ++ch) {
            const uint32_t cb = (uint32_t)ch * 32u;
            uint32_t af[2][4];
            #pragma unroll
            for (int mi = 0; mi < 2; ++mi)
                ldm_x4(af[mi][0], af[mi][1], af[mi][2], af[mi][3], aoffs[mi] + ak + cb);
            uint32_t r0, r1, r2, r3;
            ldm_x4(r0, r1, r2, r3, boff + bk + cb);
            uint32_t bf[2][2] = {{r0, r2}, {r1, r3}};
            #pragma unroll
            for (int mi = 0; mi < 2; ++mi)
                #pragma unroll
                for (int ni = 0; ni < 2; ++ni)
                    mma16816(acc[mi][ni], af[mi], bf[ni]);
        }
    }

    const int g = lane >> 2, q = lane & 3;
    #pragma unroll
    for (int mi = 0; mi < 2; ++mi)
        #pragma unroll
        for (int h = 0; h < 2; ++h) {
            int co = co0 + mi * 16 + g + h * 8;
            float bv = bias[(size_t)(b * Cn + co) * Ln + tile];
            #pragma unroll
            for (int ni = 0; ni < 2; ++ni) {
                int s = s0 + ni * 8 + q * 2;
                float v0 = acc[mi][ni][2 * h]     + bv;
                float v1 = acc[mi][ni][2 * h + 1] + bv;
                v0 = fmaxf(v0, SLOPE * v0);
                v1 = fmaxf(v1, SLOPE * v1);
                size_t off = (size_t)(b * Cn + co) * Tn + (size_t)tile * 128 + s;
                *(__half2*)(dst + off) = __floats2half2_rn(v0, v1);
            }
        }
}

// ---- dconv: 256-wide CTA, 32x32 warp tiles, two-half conflict-free staging ----
__global__ __launch_bounds__(NT, 1)
void dconv_kernel(const __half* __restrict__ src, const __half* __restrict__ Aw,
                  const float* __restrict__ conv_b, float* __restrict__ out) {
    extern __shared__ char sm[];
    const uint32_t smb = smem_u32(sm);
    const int tid = threadIdx.x;
    const int b = blockIdx.x >> 7, tt = blockIdx.x & 127;
    const int t0 = tt * 256;

    // window: xT rows c in [0,262), t = t0 - 3 + c; staged in two halves via fp32 scratch
    float* ws = (float*)(sm + DSOFF);
    __half* xh = (__half*)sm;
    #pragma unroll
    for (int half = 0; half < 2; ++half) {
        const int cbase = half * 131;
        // stage fp32 half (coalesced gmem reads, stride-1 smem writes)
        for (int i = tid; i < Cn * 131; i += NT) {
            int ci = i / 131, c = i - ci * 131;
            int t = t0 - 3 + cbase + c;
            ws[ci * WSTR2 + c] = (t >= 0 && t < Tn)
                ? __half2float(src[(size_t)(b * Cn + ci) * Tn + t]) : 0.f;
        }
        __syncthreads();
        // transpose half -> xT (stride-131 reads conflict-free; row-major fp16 writes)
        for (int i = tid; i < 131 * Cn; i += NT) {
            int c = i >> 7, ci = i & 127;
            xh[(cbase + c) * 136 + ci] = __float2half_rn(ws[ci * WSTR2 + c]);
        }
        __syncthreads();
    }

    // cp.async A over the (now dead) scratch region — gA2 is L2-resident
    {
        const uint4* sA = (const uint4*)Aw;
        #pragma unroll
        for (int j = 0; j < 6; ++j) {
            int i = tid + j * NT;
            int k = i >> 11, r = i & 2047;
            int co = r >> 4, c8 = (r & 15) << 3;
            cpasync16(smb + DSOFF + (uint32_t)k * ATILE
                      + (uint32_t)co * 272u + (uint32_t)c8 * 2u, sA + i);
        }
        cp_commit();
    }
    cp_wait0();
    __syncthreads();

    const int warp = tid >> 5, lane = tid & 31;
    const int co0 = (warp >> 3) * 32, s0 = (warp & 7) * 32;
    const uint32_t lrow = lane & 15, lcol = (uint32_t)(lane >> 4) << 4;

    uint32_t aoffs[2], boffs[2];
    #pragma unroll
    for (int mi = 0; mi < 2; ++mi)
        aoffs[mi] = smb + DSOFF + (uint32_t)(co0 + mi * 16 + (int)lrow) * 272u + lcol;
    #pragma unroll
    for (int p = 0; p < 2; ++p)
        boffs[p] = smb + (uint32_t)(s0 + p * 16 + (int)lrow) * 272u + lcol;

    float acc[2][4][4];
    #pragma unroll
    for (int mi = 0; mi < 2; ++mi)
        #pragma unroll
        for (int ni = 0; ni < 4; ++ni)
            #pragma unroll
            for (int q = 0; q < 4; ++q) acc[mi][ni][q] = 0.f;

    #pragma unroll
    for (int k = 0; k < 3; ++k) {
        const uint32_t ak = (uint32_t)k * ATILE;
        const uint32_t bk = (uint32_t)(3 * k) * 272u;
        #pragma unroll
        for (int ch = 0; ch < 8; ++ch) {
            const uint32_t cb = (uint32_t)ch * 32u;
            uint32_t af[2][4];
            #pragma unroll
            for (int mi = 0; mi < 2; ++mi)
                ldm_x4(af[mi][0], af[mi][1], af[mi][2], af[mi][3], aoffs[mi] + ak + cb);
            #pragma unroll
            for (int p = 0; p < 2; ++p) {
                uint32_t r0, r1, r2, r3;
                ldm_x4(r0, r1, r2, r3, boffs[p] + bk + cb);
                uint32_t bf[2][2] = {{r0, r2}, {r1, r3}};
                #pragma unroll
                for (int mi = 0; mi < 2; ++mi)
                    #pragma unroll
                    for (int nj = 0; nj < 2; ++nj)
                        mma16816(acc[mi][2 * p + nj], af[mi], bf[nj]);
            }
        }
    }

    const int g = lane >> 2, q = lane & 3;
    #pragma unroll
    for (int mi = 0; mi < 2; ++mi)
        #pragma unroll
        for (int h = 0; h < 2; ++h) {
            int co = co0 + mi * 16 + g + h * 8;
            float bv = conv_b[co];
            #pragma unroll
            for (int ni = 0; ni < 4; ++ni) {
                int s = s0 + ni * 8 + q * 2;
                float v0 = acc[mi][ni][2 * h]     + bv;
                float v1 = acc[mi][ni][2 * h + 1] + bv;
                v0 = fmaxf(v0, SLOPE * v0);
                v1 = fmaxf(v1, SLOPE * v1);
                *(float2*)(out + (size_t)(b * Cn + co) * Tn + t0 + s) = make_float2(v0, v1);
            }
        }
}

// ---- launch ----
extern "C" void kernel_launch(void* const* d_in, const int* in_sizes, int n_in,
                              void* d_out, int out_size) {
    const float* x      = (const float*)d_in[0];
    const float* weight = (const float*)d_in[1];
    const float* bias   = (const float*)d_in[2];
    const float* conv_v = (const float*)d_in[3];
    const float* conv_g = (const float*)d_in[4];
    const float* conv_b = (const float*)d_in[5];

    __half *gh_ptr, *pA, *pA2;
    cudaGetSymbolAddress((void**)&gh_ptr, g_h);
    cudaGetSymbolAddress((void**)&pA, gA);
    cudaGetSymbolAddress((void**)&pA2, gA2);

    cudaFuncSetAttribute((const void*)lvc_kernel,
                         cudaFuncAttributeMaxDynamicSharedMemorySize, SMEM_LVC);
    cudaFuncSetAttribute((const void*)dconv_kernel,
                         cudaFuncAttributeMaxDynamicSharedMemorySize, SMEM_DCV);

    wn_prep_kernel<<<1, Cn>>>(conv_v, conv_g);
    transpose_w_kernel<<<dim3(Ln / 32, Cn / 64, Bn * Cn * 3), dim3(512)>>>(weight);
    lvc_kernel<<<Bn * 256, NT, SMEM_LVC>>>(x, pA, bias, gh_ptr);
    dconv_kernel<<<Bn * 128, NT, SMEM_DCV>>>(gh_ptr, pA2, conv_b, (float*)d_out);
}

// round 10
// speedup vs baseline: 1.4832x; 1.0399x over previous
#include <cuda_runtime.h>
#include <cuda_fp16.h>
#include <cstdint>

constexpr int Bn = 8, Cn = 128, Tn = 32768, Ln = 256;
constexpr float SLOPE = 0.2f;
constexpr int NT = 1024;

// ---- device scratch ----
__device__ __half gA  [(size_t)Bn * Ln * 3 * Cn * Cn];  // lvc weight [b][l][k][co][ci] fp16
__device__ __half g_h [(size_t)Bn * Cn * Tn];           // LVC output fp16
__device__ __half gA2 [3 * Cn * Cn];                    // dconv weight [k][co][ci] fp16

// ---- helpers ----
static __device__ __forceinline__ uint32_t smem_u32(const void* p) {
    uint32_t a;
    asm("{ .reg .u64 t; cvta.to.shared.u64 t, %1; cvt.u32.u64 %0, t; }" : "=r"(a) : "l"(p));
    return a;
}
static __device__ __forceinline__ void ldm_x4(uint32_t &r0, uint32_t &r1,
                                              uint32_t &r2, uint32_t &r3, uint32_t addr) {
    asm volatile("ldmatrix.sync.aligned.m8n8.x4.shared.b16 {%0,%1,%2,%3}, [%4];"
                 : "=r"(r0), "=r"(r1), "=r"(r2), "=r"(r3) : "r"(addr));
}
static __device__ __forceinline__ void mma16816(float* c, const uint32_t* a, const uint32_t* b) {
    asm volatile("mma.sync.aligned.m16n8k16.row.col.f32.f16.f16.f32 "
                 "{%0,%1,%2,%3}, {%4,%5,%6,%7}, {%8,%9}, {%0,%1,%2,%3};"
                 : "+f"(c[0]), "+f"(c[1]), "+f"(c[2]), "+f"(c[3])
                 : "r"(a[0]), "r"(a[1]), "r"(a[2]), "r"(a[3]), "r"(b[0]), "r"(b[1]));
}
static __device__ __forceinline__ void cpasync16(uint32_t s, const void* g) {
    asm volatile("cp.async.cg.shared.global [%0], [%1], 16;" :: "r"(s), "l"(g));
}
static __device__ __forceinline__ void cp_commit() {
    asm volatile("cp.async.commit_group;" ::: "memory");
}
static __device__ __forceinline__ void cp_wait0() {
    asm volatile("cp.async.wait_group 0;" ::: "memory");
}
static __device__ __forceinline__ void cp_wait1() {
    asm volatile("cp.async.wait_group 1;" ::: "memory");
}

constexpr uint32_t ATILE = 34816u;          // 128 rows x 272B (one k-tile)

// ---- lvc smem: xT [0, 70176) (258 rows x 272B); A double-buffer at ABUF;
//      fp32 half-window scratch (128 x 129 fl = 66048) overlays ABUF (dead first) ----
constexpr uint32_t ABUF = 70400u;
constexpr uint32_t SMEM_LVC = ABUF + 2u * ATILE;   // 140032
constexpr int WSTRL = 129;

// ---- dconv smem (R9): xT [0, 71264) (262 rows x 272B); scratch/A at DSOFF ----
constexpr uint32_t DSOFF = 71264u;
constexpr uint32_t SMEM_DCV = DSOFF + 3u * ATILE;  // 175712
constexpr int WSTR2 = 131;

// ---- prep: weight-norm conv weight -> fp16 [k][co][ci] ----
__global__ void wn_prep_kernel(const float* __restrict__ conv_v,
                               const float* __restrict__ conv_g) {
    __shared__ float sc[Cn];
    int co = threadIdx.x;
    float s = 0.f;
    for (int i = 0; i < Cn * 3; ++i) {
        float t = conv_v[co * (Cn * 3) + i];
        s += t * t;
    }
    sc[co] = conv_g[co] / sqrtf(s);
    __syncthreads();
    for (int i = threadIdx.x; i < 3 * Cn * Cn; i += Cn) {
        int k = i >> 14, rest = i & 16383, c2 = rest >> 7, ci = rest & 127;
        gA2[i] = __float2half_rn(conv_v[(c2 * Cn + ci) * 3 + k] * sc[c2]);
    }
}

// ---- transpose W[b][ci][co][k][l] -> gA[b][l][k][co][ci] fp16 (vectorized) ----
__global__ __launch_bounds__(512)
void transpose_w_kernel(const float* __restrict__ W) {
    __shared__ float tile[64][36];            // padded: 144B rows, 16B aligned
    int z = blockIdx.z;
    int k = z % 3, co = (z / 3) & 127, b = z / (3 * Cn);
    int l0 = blockIdx.x * 32, ci0 = blockIdx.y * 64;
    const int tid = threadIdx.x;

    // reads: thread -> (ci row, 4 l floats) via LDG.128
    {
        int cir = tid >> 3, l4 = (tid & 7) * 4;
        float4 v = *(const float4*)(W +
            ((((size_t)b * Cn + ci0 + cir) * Cn + co) * 3 + k) * Ln + l0 + l4);
        *(float4*)&tile[cir][l4] = v;
    }
    __syncthreads();
    // writes: thread -> (l row, 4 ci) as uint2 fp16
    {
        int lr = tid >> 4, cig = (tid & 15) * 4;
        __half2 h0 = __floats2half2_rn(tile[cig][lr],     tile[cig + 1][lr]);
        __half2 h1 = __floats2half2_rn(tile[cig + 2][lr], tile[cig + 3][lr]);
        uint2 w;
        w.x = *(uint32_t*)&h0;
        w.y = *(uint32_t*)&h1;
        size_t o = ((((size_t)b * Ln + l0 + lr) * 3 + k) * Cn + co) * Cn + ci0 + cig;
        *(uint2*)(gA + o) = w;
    }
}

// ---- LVC: 256-wide CTA, two 128-phases, 2-deep k-tile cp.async pipeline ----
__global__ __launch_bounds__(NT, 1)
void lvc_kernel(const float* __restrict__ x, const __half* __restrict__ Aw,
                const float* __restrict__ bias, __half* __restrict__ dst) {
    extern __shared__ char sm[];
    const uint32_t smb = smem_u32(sm);
    const int tid = threadIdx.x;
    const int b = blockIdx.x >> 7, tt = blockIdx.x & 127;
    const int t0 = tt * 256;

    // window: xT rows c in [0,258), t = t0 - 1 + c; two halves via fp32 scratch
    {
        float* ws = (float*)(sm + ABUF);
        __half* xh = (__half*)sm;
        #pragma unroll
        for (int half = 0; half < 2; ++half) {
            const int cbase = half * 129;
            for (int i = tid; i < Cn * 129; i += NT) {
                int ci = i / 129, c = i - ci * 129;
                int t = t0 - 1 + cbase + c;
                ws[ci * WSTRL + c] = (t >= 0 && t < Tn)
                    ? x[(size_t)(b * Cn + ci) * Tn + t] : 0.f;
            }
            __syncthreads();
            for (int i = tid; i < 129 * 64; i += NT) {
                int c = i >> 6, ci2 = (i & 63) * 2;
                __half2 hv = __floats2half2_rn(ws[ci2 * WSTRL + c],
                                               ws[(ci2 + 1) * WSTRL + c]);
                *(__half2*)(sm + (uint32_t)(cbase + c) * 272u + (uint32_t)ci2 * 2u) = hv;
            }
            __syncthreads();
        }
    }

    // A k-tile stager: kt in [0,6) = phase*3 + k; double-buffered by kt parity
    auto stage_kt = [&](int kt) {
        int p = kt / 3, k = kt - 3 * p;
        const uint4* sA = (const uint4*)(Aw +
            ((size_t)(b * Ln + tt * 2 + p) * 3 + k) * 16384);
        uint32_t buf = smb + ABUF + (uint32_t)(kt & 1) * ATILE;
        #pragma unroll
        for (int j = 0; j < 2; ++j) {
            int i = tid + j * NT;
            int co = i >> 4, c8 = (i & 15) << 3;
            cpasync16(buf + (uint32_t)co * 272u + (uint32_t)c8 * 2u, sA + i);
        }
        cp_commit();
    };
    stage_kt(0);
    stage_kt(1);

    const int warp = tid >> 5, lane = tid & 31;
    const int co0 = (warp >> 3) * 32, s0 = (warp & 7) * 16;
    const uint32_t lrow = lane & 15, lcol = (uint32_t)(lane >> 4) << 4;
    const int g = lane >> 2, q = lane & 3;
    const uint32_t arow = (uint32_t)(co0 + (int)lrow) * 272u + lcol;

    #pragma unroll
    for (int p = 0; p < 2; ++p) {
        float acc[2][2][4];
        #pragma unroll
        for (int mi = 0; mi < 2; ++mi)
            #pragma unroll
            for (int ni = 0; ni < 2; ++ni)
                #pragma unroll
                for (int qq = 0; qq < 4; ++qq) acc[mi][ni][qq] = 0.f;

        #pragma unroll
        for (int k = 0; k < 3; ++k) {
            const int kt = 3 * p + k;
            if (kt == 5) cp_wait0(); else cp_wait1();
            __syncthreads();

            const uint32_t abase = smb + ABUF + (uint32_t)(kt & 1) * ATILE + arow;
            const uint32_t bbase = smb + (uint32_t)(p * 128 + k + s0 + (int)lrow) * 272u + lcol;
            #pragma unroll
            for (int ch = 0; ch < 8; ++ch) {
                const uint32_t cb = (uint32_t)ch * 32u;
                uint32_t af[2][4];
                #pragma unroll
                for (int mi = 0; mi < 2; ++mi)
                    ldm_x4(af[mi][0], af[mi][1], af[mi][2], af[mi][3],
                           abase + (uint32_t)(mi * 16) * 272u + cb);
                uint32_t r0, r1, r2, r3;
                ldm_x4(r0, r1, r2, r3, bbase + cb);
                uint32_t bf[2][2] = {{r0, r2}, {r1, r3}};
                #pragma unroll
                for (int mi = 0; mi < 2; ++mi)
                    #pragma unroll
                    for (int ni = 0; ni < 2; ++ni)
                        mma16816(acc[mi][ni], af[mi], bf[ni]);
            }
            __syncthreads();
            if (kt < 4) stage_kt(kt + 2);
        }

        // epilogue phase p: bias + leaky -> fp16 g_h
        const int l = tt * 2 + p;
        #pragma unroll
        for (int mi = 0; mi < 2; ++mi)
            #pragma unroll
            for (int h = 0; h < 2; ++h) {
                int co = co0 + mi * 16 + g + h * 8;
                float bv = bias[(size_t)(b * Cn + co) * Ln + l];
                #pragma unroll
                for (int ni = 0; ni < 2; ++ni) {
                    int s = s0 + ni * 8 + q * 2;
                    float v0 = acc[mi][ni][2 * h]     + bv;
                    float v1 = acc[mi][ni][2 * h + 1] + bv;
                    v0 = fmaxf(v0, SLOPE * v0);
                    v1 = fmaxf(v1, SLOPE * v1);
                    size_t off = (size_t)(b * Cn + co) * Tn + t0 + p * 128 + s;
                    *(__half2*)(dst + off) = __floats2half2_rn(v0, v1);
                }
            }
    }
}

// ---- dconv: R9 verbatim (256-wide, 32x32 warp tiles) ----
__global__ __launch_bounds__(NT, 1)
void dconv_kernel(const __half* __restrict__ src, const __half* __restrict__ Aw,
                  const float* __restrict__ conv_b, float* __restrict__ out) {
    extern __shared__ char sm[];
    const uint32_t smb = smem_u32(sm);
    const int tid = threadIdx.x;
    const int b = blockIdx.x >> 7, tt = blockIdx.x & 127;
    const int t0 = tt * 256;

    float* ws = (float*)(sm + DSOFF);
    __half* xh = (__half*)sm;
    #pragma unroll
    for (int half = 0; half < 2; ++half) {
        const int cbase = half * 131;
        for (int i = tid; i < Cn * 131; i += NT) {
            int ci = i / 131, c = i - ci * 131;
            int t = t0 - 3 + cbase + c;
            ws[ci * WSTR2 + c] = (t >= 0 && t < Tn)
                ? __half2float(src[(size_t)(b * Cn + ci) * Tn + t]) : 0.f;
        }
        __syncthreads();
        for (int i = tid; i < 131 * Cn; i += NT) {
            int c = i >> 7, ci = i & 127;
            xh[(cbase + c) * 136 + ci] = __float2half_rn(ws[ci * WSTR2 + c]);
        }
        __syncthreads();
    }

    {
        const uint4* sA = (const uint4*)Aw;
        #pragma unroll
        for (int j = 0; j < 6; ++j) {
            int i = tid + j * NT;
            int k = i >> 11, r = i & 2047;
            int co = r >> 4, c8 = (r & 15) << 3;
            cpasync16(smb + DSOFF + (uint32_t)k * ATILE
                      + (uint32_t)co * 272u + (uint32_t)c8 * 2u, sA + i);
        }
        cp_commit();
    }
    cp_wait0();
    __syncthreads();

    const int warp = tid >> 5, lane = tid & 31;
    const int co0 = (warp >> 3) * 32, s0 = (warp & 7) * 32;
    const uint32_t lrow = lane & 15, lcol = (uint32_t)(lane >> 4) << 4;

    uint32_t aoffs[2], boffs[2];
    #pragma unroll
    for (int mi = 0; mi < 2; ++mi)
        aoffs[mi] = smb + DSOFF + (uint32_t)(co0 + mi * 16 + (int)lrow) * 272u + lcol;
    #pragma unroll
    for (int p = 0; p < 2; ++p)
        boffs[p] = smb + (uint32_t)(s0 + p * 16 + (int)lrow) * 272u + lcol;

    float acc[2][4][4];
    #pragma unroll
    for (int mi = 0; mi < 2; ++mi)
        #pragma unroll
        for (int ni = 0; ni < 4; ++ni)
            #pragma unroll
            for (int q = 0; q < 4; ++q) acc[mi][ni][q] = 0.f;

    #pragma unroll
    for (int k = 0; k < 3; ++k) {
        const uint32_t ak = (uint32_t)k * ATILE;
        const uint32_t bk = (uint32_t)(3 * k) * 272u;
        #pragma unroll
        for (int ch = 0; ch < 8; ++ch) {
            const uint32_t cb = (uint32_t)ch * 32u;
            uint32_t af[2][4];
            #pragma unroll
            for (int mi = 0; mi < 2; ++mi)
                ldm_x4(af[mi][0], af[mi][1], af[mi][2], af[mi][3], aoffs[mi] + ak + cb);
            #pragma unroll
            for (int p = 0; p < 2; ++p) {
                uint32_t r0, r1, r2, r3;
                ldm_x4(r0, r1, r2, r3, boffs[p] + bk + cb);
                uint32_t bf[2][2] = {{r0, r2}, {r1, r3}};
                #pragma unroll
                for (int mi = 0; mi < 2; ++mi)
                    #pragma unroll
                    for (int nj = 0; nj < 2; ++nj)
                        mma16816(acc[mi][2 * p + nj], af[mi], bf[nj]);
            }
        }
    }

    const int g = lane >> 2, q = lane & 3;
    #pragma unroll
    for (int mi = 0; mi < 2; ++mi)
        #pragma unroll
        for (int h = 0; h < 2; ++h) {
            int co = co0 + mi * 16 + g + h * 8;
            float bv = conv_b[co];
            #pragma unroll
            for (int ni = 0; ni < 4; ++ni) {
                int s = s0 + ni * 8 + q * 2;
                float v0 = acc[mi][ni][2 * h]     + bv;
                float v1 = acc[mi][ni][2 * h + 1] + bv;
                v0 = fmaxf(v0, SLOPE * v0);
                v1 = fmaxf(v1, SLOPE * v1);
                *(float2*)(out + (size_t)(b * Cn + co) * Tn + t0 + s) = make_float2(v0, v1);
            }
        }
}

// ---- launch ----
extern "C" void kernel_launch(void* const* d_in, const int* in_sizes, int n_in,
                              void* d_out, int out_size) {
    const float* x      = (const float*)d_in[0];
    const float* weight = (const float*)d_in[1];
    const float* bias   = (const float*)d_in[2];
    const float* conv_v = (const float*)d_in[3];
    const float* conv_g = (const float*)d_in[4];
    const float* conv_b = (const float*)d_in[5];

    __half *gh_ptr, *pA, *pA2;
    cudaGetSymbolAddress((void**)&gh_ptr, g_h);
    cudaGetSymbolAddress((void**)&pA, gA);
    cudaGetSymbolAddress((void**)&pA2, gA2);

    cudaFuncSetAttribute((const void*)lvc_kernel,
                         cudaFuncAttributeMaxDynamicSharedMemorySize, SMEM_LVC);
    cudaFuncSetAttribute((const void*)dconv_kernel,
                         cudaFuncAttributeMaxDynamicSharedMemorySize, SMEM_DCV);

    wn_prep_kernel<<<1, Cn>>>(conv_v, conv_g);
    transpose_w_kernel<<<dim3(Ln / 32, Cn / 64, Bn * Cn * 3), dim3(512)>>>(weight);
    lvc_kernel<<<Bn * 128, NT, SMEM_LVC>>>(x, pA, bias, gh_ptr);
    dconv_kernel<<<Bn * 128, NT, SMEM_DCV>>>(gh_ptr, pA2, conv_b, (float*)d_out);
}

// round 11
// speedup vs baseline: 1.6342x; 1.1018x over previous
#include <cuda_runtime.h>
#include <cuda_fp16.h>
#include <cstdint>

constexpr int Bn = 8, Cn = 128, Tn = 32768, Ln = 256;
constexpr float SLOPE = 0.2f;
constexpr int NT = 1024;

// ---- device scratch ----
__device__ __half gA  [(size_t)Bn * Ln * 3 * Cn * Cn];  // lvc weight [b][l][k][co][ci] fp16
__device__ __half g_h [(size_t)Bn * Cn * Tn];           // LVC output fp16, layout [b][t][co]
__device__ __half gA2 [3 * Cn * Cn];                    // dconv weight [k][co][ci] fp16

// ---- helpers ----
static __device__ __forceinline__ uint32_t smem_u32(const void* p) {
    uint32_t a;
    asm("{ .reg .u64 t; cvta.to.shared.u64 t, %1; cvt.u32.u64 %0, t; }" : "=r"(a) : "l"(p));
    return a;
}
static __device__ __forceinline__ void ldm_x4(uint32_t &r0, uint32_t &r1,
                                              uint32_t &r2, uint32_t &r3, uint32_t addr) {
    asm volatile("ldmatrix.sync.aligned.m8n8.x4.shared.b16 {%0,%1,%2,%3}, [%4];"
                 : "=r"(r0), "=r"(r1), "=r"(r2), "=r"(r3) : "r"(addr));
}
static __device__ __forceinline__ void mma16816(float* c, const uint32_t* a, const uint32_t* b) {
    asm volatile("mma.sync.aligned.m16n8k16.row.col.f32.f16.f16.f32 "
                 "{%0,%1,%2,%3}, {%4,%5,%6,%7}, {%8,%9}, {%0,%1,%2,%3};"
                 : "+f"(c[0]), "+f"(c[1]), "+f"(c[2]), "+f"(c[3])
                 : "r"(a[0]), "r"(a[1]), "r"(a[2]), "r"(a[3]), "r"(b[0]), "r"(b[1]));
}
static __device__ __forceinline__ void cpasync16(uint32_t s, const void* g) {
    asm volatile("cp.async.cg.shared.global [%0], [%1], 16;" :: "r"(s), "l"(g));
}
static __device__ __forceinline__ void cp_commit() {
    asm volatile("cp.async.commit_group;" ::: "memory");
}
static __device__ __forceinline__ void cp_wait0() {
    asm volatile("cp.async.wait_group 0;" ::: "memory");
}
static __device__ __forceinline__ void cp_wait1() {
    asm volatile("cp.async.wait_group 1;" ::: "memory");
}

constexpr uint32_t ATILE = 34816u;          // 128 rows x 272B (one k-tile)

// ---- lvc smem: xT [0, 70176); A double-buffer at ABUF; EP bounce at EPOFF;
//      fp32 half-window scratch (128 x 129 = 66048B... x4=258KB? no: floats) overlays ABUF ----
constexpr uint32_t ABUF  = 70400u;
constexpr uint32_t EPOFF = ABUF + 2u * ATILE;       // 140032
constexpr uint32_t SMEM_LVC = EPOFF + ATILE;        // 174848
constexpr int WSTRL = 129;

// ---- dconv smem: xT [0, 71264) (262 rows x 272B); A at DSOFF ----
constexpr uint32_t DSOFF = 71264u;
constexpr uint32_t SMEM_DCV = DSOFF + 3u * ATILE;   // 175712

// ---- prep: weight-norm conv weight -> fp16 [k][co][ci] ----
__global__ void wn_prep_kernel(const float* __restrict__ conv_v,
                               const float* __restrict__ conv_g) {
    __shared__ float sc[Cn];
    int co = threadIdx.x;
    float s = 0.f;
    for (int i = 0; i < Cn * 3; ++i) {
        float t = conv_v[co * (Cn * 3) + i];
        s += t * t;
    }
    sc[co] = conv_g[co] / sqrtf(s);
    __syncthreads();
    for (int i = threadIdx.x; i < 3 * Cn * Cn; i += Cn) {
        int k = i >> 14, rest = i & 16383, c2 = rest >> 7, ci = rest & 127;
        gA2[i] = __float2half_rn(conv_v[(c2 * Cn + ci) * 3 + k] * sc[c2]);
    }
}

// ---- transpose W[b][ci][co][k][l] -> gA[b][l][k][co][ci] fp16 (vectorized) ----
__global__ __launch_bounds__(512)
void transpose_w_kernel(const float* __restrict__ W) {
    __shared__ float tile[64][36];
    int z = blockIdx.z;
    int k = z % 3, co = (z / 3) & 127, b = z / (3 * Cn);
    int l0 = blockIdx.x * 32, ci0 = blockIdx.y * 64;
    const int tid = threadIdx.x;
    {
        int cir = tid >> 3, l4 = (tid & 7) * 4;
        float4 v = *(const float4*)(W +
            ((((size_t)b * Cn + ci0 + cir) * Cn + co) * 3 + k) * Ln + l0 + l4);
        *(float4*)&tile[cir][l4] = v;
    }
    __syncthreads();
    {
        int lr = tid >> 4, cig = (tid & 15) * 4;
        __half2 h0 = __floats2half2_rn(tile[cig][lr],     tile[cig + 1][lr]);
        __half2 h1 = __floats2half2_rn(tile[cig + 2][lr], tile[cig + 3][lr]);
        uint2 w;
        w.x = *(uint32_t*)&h0;
        w.y = *(uint32_t*)&h1;
        size_t o = ((((size_t)b * Ln + l0 + lr) * 3 + k) * Cn + co) * Cn + ci0 + cig;
        *(uint2*)(gA + o) = w;
    }
}

// ---- LVC: 256-wide CTA, two 128-phases, 2-deep k-pipeline, transposed epilogue ----
__global__ __launch_bounds__(NT, 1)
void lvc_kernel(const float* __restrict__ x, const __half* __restrict__ Aw,
                const float* __restrict__ bias, __half* __restrict__ dstT) {
    extern __shared__ char sm[];
    const uint32_t smb = smem_u32(sm);
    const int tid = threadIdx.x;
    const int b = blockIdx.x >> 7, tt = blockIdx.x & 127;
    const int t0 = tt * 256;

    // window: xT rows c in [0,258), t = t0 - 1 + c; two halves via fp32 scratch (over ABUF)
    {
        float* ws = (float*)(sm + ABUF);
        #pragma unroll
        for (int half = 0; half < 2; ++half) {
            const int cbase = half * 129;
            for (int i = tid; i < Cn * 129; i += NT) {
                int ci = i / 129, c = i - ci * 129;
                int t = t0 - 1 + cbase + c;
                ws[ci * WSTRL + c] = (t >= 0 && t < Tn)
                    ? x[(size_t)(b * Cn + ci) * Tn + t] : 0.f;
            }
            __syncthreads();
            for (int i = tid; i < 129 * 64; i += NT) {
                int c = i >> 6, ci2 = (i & 63) * 2;
                __half2 hv = __floats2half2_rn(ws[ci2 * WSTRL + c],
                                               ws[(ci2 + 1) * WSTRL + c]);
                *(__half2*)(sm + (uint32_t)(cbase + c) * 272u + (uint32_t)ci2 * 2u) = hv;
            }
            __syncthreads();
        }
    }

    auto stage_kt = [&](int kt) {
        int p = kt / 3, k = kt - 3 * p;
        const uint4* sA = (const uint4*)(Aw +
            ((size_t)(b * Ln + tt * 2 + p) * 3 + k) * 16384);
        uint32_t buf = smb + ABUF + (uint32_t)(kt & 1) * ATILE;
        #pragma unroll
        for (int j = 0; j < 2; ++j) {
            int i = tid + j * NT;
            int co = i >> 4, c8 = (i & 15) << 3;
            cpasync16(buf + (uint32_t)co * 272u + (uint32_t)c8 * 2u, sA + i);
        }
        cp_commit();
    };
    stage_kt(0);
    stage_kt(1);

    const int warp = tid >> 5, lane = tid & 31;
    const int co0 = (warp >> 3) * 32, s0 = (warp & 7) * 16;
    const uint32_t lrow = lane & 15, lcol = (uint32_t)(lane >> 4) << 4;
    const int g = lane >> 2, q = lane & 3;
    const uint32_t arow = (uint32_t)(co0 + (int)lrow) * 272u + lcol;
    __half* ep = (__half*)(sm + EPOFF);

    #pragma unroll
    for (int p = 0; p < 2; ++p) {
        float acc[2][2][4];
        #pragma unroll
        for (int mi = 0; mi < 2; ++mi)
            #pragma unroll
            for (int ni = 0; ni < 2; ++ni)
                #pragma unroll
                for (int qq = 0; qq < 4; ++qq) acc[mi][ni][qq] = 0.f;

        #pragma unroll
        for (int k = 0; k < 3; ++k) {
            const int kt = 3 * p + k;
            if (kt == 5) cp_wait0(); else cp_wait1();
            __syncthreads();

            const uint32_t abase = smb + ABUF + (uint32_t)(kt & 1) * ATILE + arow;
            const uint32_t bbase = smb + (uint32_t)(p * 128 + k + s0 + (int)lrow) * 272u + lcol;
            #pragma unroll
            for (int ch = 0; ch < 8; ++ch) {
                const uint32_t cb = (uint32_t)ch * 32u;
                uint32_t af[2][4];
                #pragma unroll
                for (int mi = 0; mi < 2; ++mi)
                    ldm_x4(af[mi][0], af[mi][1], af[mi][2], af[mi][3],
                           abase + (uint32_t)(mi * 16) * 272u + cb);
                uint32_t r0, r1, r2, r3;
                ldm_x4(r0, r1, r2, r3, bbase + cb);
                uint32_t bf[2][2] = {{r0, r2}, {r1, r3}};
                #pragma unroll
                for (int mi = 0; mi < 2; ++mi)
                    #pragma unroll
                    for (int ni = 0; ni < 2; ++ni)
                        mma16816(acc[mi][ni], af[mi], bf[ni]);
            }
            __syncthreads();
            if (kt < 4) stage_kt(kt + 2);
        }

        // epilogue: bias + leaky -> EP smem [s][co] -> coalesced rows of g_hT[b][t][co]
        const int l = tt * 2 + p;
        #pragma unroll
        for (int mi = 0; mi < 2; ++mi)
            #pragma unroll
            for (int h = 0; h < 2; ++h) {
                int co = co0 + mi * 16 + g + h * 8;
                float bv = bias[(size_t)(b * Cn + co) * Ln + l];
                #pragma unroll
                for (int ni = 0; ni < 2; ++ni) {
                    int s = s0 + ni * 8 + q * 2;
                    float v0 = acc[mi][ni][2 * h]     + bv;
                    float v1 = acc[mi][ni][2 * h + 1] + bv;
                    v0 = fmaxf(v0, SLOPE * v0);
                    v1 = fmaxf(v1, SLOPE * v1);
                    ep[(uint32_t)s * 136u + (uint32_t)co]       = __float2half_rn(v0);
                    ep[(uint32_t)(s + 1) * 136u + (uint32_t)co] = __float2half_rn(v1);
                }
            }
        __syncthreads();
        {
            __half* dbase = dstT + ((size_t)b * Tn + t0 + p * 128) * 128;
            #pragma unroll
            for (int j = 0; j < 2; ++j) {
                int i = tid + j * NT;        // [0, 2048): row(128) x chunk(16 of 16B)
                int row = i >> 4, chunk = i & 15;
                uint4 v = *(uint4*)(sm + EPOFF + (uint32_t)row * 272u + (uint32_t)chunk * 16u);
                *(uint4*)(dbase + (size_t)row * 128 + chunk * 8) = v;
            }
        }
        // next phase's first mainloop sync orders EP reuse; no extra barrier needed
    }
}

// ---- dconv: 256-wide, 32x32 warp tiles, pure-cp.async window (no transpose) ----
__global__ __launch_bounds__(NT, 1)
void dconv_kernel(const __half* __restrict__ srcT, const __half* __restrict__ Aw,
                  const float* __restrict__ conv_b, float* __restrict__ out) {
    extern __shared__ char sm[];
    const uint32_t smb = smem_u32(sm);
    const int tid = threadIdx.x;
    const int b = blockIdx.x >> 7, tt = blockIdx.x & 127;
    const int t0 = tt * 256;

    // window: xT rows c in [0,262), t = t0-3+c — direct cp.async of g_hT rows
    for (int i = tid; i < 262 * 16; i += NT) {
        int row = i >> 4, chunk = i & 15;
        int t = t0 - 3 + row;
        uint32_t d = smb + (uint32_t)row * 272u + (uint32_t)chunk * 16u;
        if (t >= 0 && t < Tn)
            cpasync16(d, srcT + ((size_t)b * Tn + t) * 128 + chunk * 8);
        else
            *(uint4*)(sm + (uint32_t)row * 272u + (uint32_t)chunk * 16u) =
                make_uint4(0, 0, 0, 0);
    }
    // A (L2-resident, 96KB)
    {
        const uint4* sA = (const uint4*)Aw;
        #pragma unroll
        for (int j = 0; j < 6; ++j) {
            int i = tid + j * NT;
            int k = i >> 11, r = i & 2047;
            int co = r >> 4, c8 = (r & 15) << 3;
            cpasync16(smb + DSOFF + (uint32_t)k * ATILE
                      + (uint32_t)co * 272u + (uint32_t)c8 * 2u, sA + i);
        }
    }
    cp_commit();
    cp_wait0();
    __syncthreads();

    const int warp = tid >> 5, lane = tid & 31;
    const int co0 = (warp >> 3) * 32, s0 = (warp & 7) * 32;
    const uint32_t lrow = lane & 15, lcol = (uint32_t)(lane >> 4) << 4;

    uint32_t aoffs[2], boffs[2];
    #pragma unroll
    for (int mi = 0; mi < 2; ++mi)
        aoffs[mi] = smb + DSOFF + (uint32_t)(co0 + mi * 16 + (int)lrow) * 272u + lcol;
    #pragma unroll
    for (int p = 0; p < 2; ++p)
        boffs[p] = smb + (uint32_t)(s0 + p * 16 + (int)lrow) * 272u + lcol;

    float acc[2][4][4];
    #pragma unroll
    for (int mi = 0; mi < 2; ++mi)
        #pragma unroll
        for (int ni = 0; ni < 4; ++ni)
            #pragma unroll
            for (int q = 0; q < 4; ++q) acc[mi][ni][q] = 0.f;

    #pragma unroll
    for (int k = 0; k < 3; ++k) {
        const uint32_t ak = (uint32_t)k * ATILE;
        const uint32_t bk = (uint32_t)(3 * k) * 272u;
        #pragma unroll
        for (int ch = 0; ch < 8; ++ch) {
            const uint32_t cb = (uint32_t)ch * 32u;
            uint32_t af[2][4];
            #pragma unroll
            for (int mi = 0; mi < 2; ++mi)
                ldm_x4(af[mi][0], af[mi][1], af[mi][2], af[mi][3], aoffs[mi] + ak + cb);
            #pragma unroll
            for (int p = 0; p < 2; ++p) {
                uint32_t r0, r1, r2, r3;
                ldm_x4(r0, r1, r2, r3, boffs[p] + bk + cb);
                uint32_t bf[2][2] = {{r0, r2}, {r1, r3}};
                #pragma unroll
                for (int mi = 0; mi < 2; ++mi)
                    #pragma unroll
                    for (int nj = 0; nj < 2; ++nj)
                        mma16816(acc[mi][2 * p + nj], af[mi], bf[nj]);
            }
        }
    }

    const int g = lane >> 2, q = lane & 3;
    #pragma unroll
    for (int mi = 0; mi < 2; ++mi)
        #pragma unroll
        for (int h = 0; h < 2; ++h) {
            int co = co0 + mi * 16 + g + h * 8;
            float bv = conv_b[co];
            #pragma unroll
            for (int ni = 0; ni < 4; ++ni) {
                int s = s0 + ni * 8 + q * 2;
                float v0 = acc[mi][ni][2 * h]     + bv;
                float v1 = acc[mi][ni][2 * h + 1] + bv;
                v0 = fmaxf(v0, SLOPE * v0);
                v1 = fmaxf(v1, SLOPE * v1);
                *(float2*)(out + (size_t)(b * Cn + co) * Tn + t0 + s) = make_float2(v0, v1);
            }
        }
}

// ---- launch ----
extern "C" void kernel_launch(void* const* d_in, const int* in_sizes, int n_in,
                              void* d_out, int out_size) {
    const float* x      = (const float*)d_in[0];
    const float* weight = (const float*)d_in[1];
    const float* bias   = (const float*)d_in[2];
    const float* conv_v = (const float*)d_in[3];
    const float* conv_g = (const float*)d_in[4];
    const float* conv_b = (const float*)d_in[5];

    __half *gh_ptr, *pA, *pA2;
    cudaGetSymbolAddress((void**)&gh_ptr, g_h);
    cudaGetSymbolAddress((void**)&pA, gA);
    cudaGetSymbolAddress((void**)&pA2, gA2);

    cudaFuncSetAttribute((const void*)lvc_kernel,
                         cudaFuncAttributeMaxDynamicSharedMemorySize, SMEM_LVC);
    cudaFuncSetAttribute((const void*)dconv_kernel,
                         cudaFuncAttributeMaxDynamicSharedMemorySize, SMEM_DCV);

    wn_prep_kernel<<<1, Cn>>>(conv_v, conv_g);
    transpose_w_kernel<<<dim3(Ln / 32, Cn / 64, Bn * Cn * 3), dim3(512)>>>(weight);
    lvc_kernel<<<Bn * 128, NT, SMEM_LVC>>>(x, pA, bias, gh_ptr);
    dconv_kernel<<<Bn * 128, NT, SMEM_DCV>>>(gh_ptr, pA2, conv_b, (float*)d_out);
}